// round 6
// baseline (speedup 1.0000x reference)
#include <cuda_runtime.h>

// Scratch via __device__ globals (no allocations allowed).
#define NBLOCKS 1184   // 148 SMs x 8 blocks
__device__ double g_partials[NBLOCKS];
__device__ unsigned int g_retire_count = 0;  // reset to 0 by last block each run

__device__ __forceinline__ float4 ldcs4(const float4* p) {
    return __ldcs(p);
}

__device__ __forceinline__ float dot4(float4 a, float4 b, float acc) {
    acc = fmaf(a.x, b.x, acc);
    acc = fmaf(a.y, b.y, acc);
    acc = fmaf(a.z, b.z, acc);
    acc = fmaf(a.w, b.w, acc);
    return acc;
}

// Single fused kernel: grid-stride, unroll-4 front-batched float4 streaming
// loads (8 independent LDG.128 in flight per thread), per-block partial into
// a dedicated slot, last retiring block reduces partials and writes the mean.
__global__ void __launch_bounds__(512)
bins_combiner_kernel(const float4* __restrict__ p4,
                     const float4* __restrict__ c4,
                     int n4,
                     const float* __restrict__ p_tail,
                     const float* __restrict__ c_tail,
                     int n_tail,
                     float* __restrict__ out,
                     double inv_rows) {
    float acc0 = 0.0f, acc1 = 0.0f, acc2 = 0.0f, acc3 = 0.0f;

    int idx    = blockIdx.x * blockDim.x + threadIdx.x;   // < 606208
    int stride = gridDim.x * blockDim.x;                  // 606208

    int i = idx;
    // Main unroll-4 loop: 8 independent 16B loads front-batched.
    for (; i + 3 * stride < n4; i += 4 * stride) {
        float4 a0 = ldcs4(p4 + i);
        float4 b0 = ldcs4(c4 + i);
        float4 a1 = ldcs4(p4 + i + stride);
        float4 b1 = ldcs4(c4 + i + stride);
        float4 a2 = ldcs4(p4 + i + 2 * stride);
        float4 b2 = ldcs4(c4 + i + 2 * stride);
        float4 a3 = ldcs4(p4 + i + 3 * stride);
        float4 b3 = ldcs4(c4 + i + 3 * stride);
        acc0 = dot4(a0, b0, acc0);
        acc1 = dot4(a1, b1, acc1);
        acc2 = dot4(a2, b2, acc2);
        acc3 = dot4(a3, b3, acc3);
    }
    // Remainder (0..3 strided elements).
    for (; i < n4; i += stride) {
        float4 a = ldcs4(p4 + i);
        float4 b = ldcs4(c4 + i);
        acc0 = dot4(a, b, acc0);
    }

    float acc = (acc0 + acc1) + (acc2 + acc3);

    // Scalar tail (first few threads of the grid).
    if (idx < n_tail) {
        acc = fmaf(p_tail[idx], c_tail[idx], acc);
    }

    // Warp reduction.
    #pragma unroll
    for (int off = 16; off > 0; off >>= 1)
        acc += __shfl_xor_sync(0xFFFFFFFFu, acc, off);

    // Block reduction via shared memory.
    __shared__ float warp_sums[16];  // 512 threads -> 16 warps
    __shared__ bool  is_last;
    int lane = threadIdx.x & 31;
    int wid  = threadIdx.x >> 5;
    if (lane == 0) warp_sums[wid] = acc;
    __syncthreads();

    if (wid == 0) {
        float v = (lane < 16) ? warp_sums[lane] : 0.0f;
        #pragma unroll
        for (int off = 16; off > 0; off >>= 1)
            v += __shfl_xor_sync(0xFFFFFFFFu, v, off);
        if (lane == 0) {
            g_partials[blockIdx.x] = (double)v;
            __threadfence();
            unsigned int prev = atomicAdd(&g_retire_count, 1u);
            is_last = (prev == gridDim.x - 1);
        }
    }
    __syncthreads();

    if (is_last) {
        __threadfence();  // acquire: make all partials visible
        double d = 0.0;
        for (unsigned int j = threadIdx.x; j < gridDim.x; j += blockDim.x)
            d += g_partials[j];
        #pragma unroll
        for (int off = 16; off > 0; off >>= 1)
            d += __shfl_xor_sync(0xFFFFFFFFu, d, off);

        __shared__ double dwarp[16];
        if (lane == 0) dwarp[wid] = d;
        __syncthreads();
        if (wid == 0) {
            double t = (lane < 16) ? dwarp[lane] : 0.0;
            #pragma unroll
            for (int off = 16; off > 0; off >>= 1)
                t += __shfl_xor_sync(0xFFFFFFFFu, t, off);
            if (lane == 0) {
                out[0] = (float)(t * inv_rows);
                __threadfence();
                g_retire_count = 0;  // reset for next graph replay
            }
        }
    }
}

extern "C" void kernel_launch(void* const* d_in, const int* in_sizes, int n_in,
                              void* d_out, int out_size) {
    const float* probs     = (const float*)d_in[0];
    const float* centroids = (const float*)d_in[1];
    float* out = (float*)d_out;

    long long n = (long long)in_sizes[0];   // N*K total elements (~1.01e8)
    const int K = 101;
    long long rows = n / K;

    int n4 = (int)(n >> 2);                 // float4 count (~25.3M, fits int)
    long long tail_start = (long long)n4 << 2;
    int n_tail = (int)(n - tail_start);

    bins_combiner_kernel<<<NBLOCKS, 512>>>(
        (const float4*)probs, (const float4*)centroids, n4,
        probs + tail_start, centroids + tail_start, n_tail,
        out, 1.0 / (double)rows);
}

// round 7
// speedup vs baseline: 1.0394x; 1.0394x over previous
#include <cuda_runtime.h>

// Scratch via __device__ globals (no allocations allowed).
#define NBLOCKS 1184   // 148 SMs x 8 blocks
__device__ double g_partials[NBLOCKS];
__device__ unsigned int g_retire_count = 0;  // reset to 0 by last block each run

// 256-bit streaming load (sm_100+): one LDG.E.256 per 8 floats.
__device__ __forceinline__ void ldg256(const float* p, float* v) {
    asm volatile(
        "ld.global.nc.v8.f32 {%0, %1, %2, %3, %4, %5, %6, %7}, [%8];"
        : "=f"(v[0]), "=f"(v[1]), "=f"(v[2]), "=f"(v[3]),
          "=f"(v[4]), "=f"(v[5]), "=f"(v[6]), "=f"(v[7])
        : "l"(p));
}

// Single fused kernel: grid-stride over 32-byte packets. Each iteration
// front-batches two independent 256-bit loads (one per stream), 16 FMAs,
// per-block partial into a dedicated slot; last retiring block reduces the
// partials and writes the mean. Graph-replayable (counter self-resets).
__global__ void __launch_bounds__(512)
bins_combiner_kernel(const float* __restrict__ p,
                     const float* __restrict__ c,
                     int n8,                      // count of 8-float packets
                     const float* __restrict__ p_tail,
                     const float* __restrict__ c_tail,
                     int n_tail,
                     float* __restrict__ out,
                     double inv_rows) {
    float acc0 = 0.0f, acc1 = 0.0f;

    int idx    = blockIdx.x * blockDim.x + threadIdx.x;
    int stride = gridDim.x * blockDim.x;

    for (int i = idx; i < n8; i += stride) {
        float a[8], b[8];
        ldg256(p + (long long)i * 8, a);
        ldg256(c + (long long)i * 8, b);
        acc0 = fmaf(a[0], b[0], acc0);
        acc1 = fmaf(a[1], b[1], acc1);
        acc0 = fmaf(a[2], b[2], acc0);
        acc1 = fmaf(a[3], b[3], acc1);
        acc0 = fmaf(a[4], b[4], acc0);
        acc1 = fmaf(a[5], b[5], acc1);
        acc0 = fmaf(a[6], b[6], acc0);
        acc1 = fmaf(a[7], b[7], acc1);
    }

    float acc = acc0 + acc1;

    // Scalar tail (first few threads of the grid). n is divisible by 8 for
    // this problem (n_tail == 0), kept for generality.
    if (idx < n_tail) {
        acc = fmaf(p_tail[idx], c_tail[idx], acc);
    }

    // Warp reduction.
    #pragma unroll
    for (int off = 16; off > 0; off >>= 1)
        acc += __shfl_xor_sync(0xFFFFFFFFu, acc, off);

    // Block reduction via shared memory.
    __shared__ float warp_sums[16];  // 512 threads -> 16 warps
    __shared__ bool  is_last;
    int lane = threadIdx.x & 31;
    int wid  = threadIdx.x >> 5;
    if (lane == 0) warp_sums[wid] = acc;
    __syncthreads();

    if (wid == 0) {
        float v = (lane < 16) ? warp_sums[lane] : 0.0f;
        #pragma unroll
        for (int off = 16; off > 0; off >>= 1)
            v += __shfl_xor_sync(0xFFFFFFFFu, v, off);
        if (lane == 0) {
            g_partials[blockIdx.x] = (double)v;
            __threadfence();
            unsigned int prev = atomicAdd(&g_retire_count, 1u);
            is_last = (prev == gridDim.x - 1);
        }
    }
    __syncthreads();

    if (is_last) {
        __threadfence();  // acquire: make all partials visible
        double d = 0.0;
        for (unsigned int j = threadIdx.x; j < gridDim.x; j += blockDim.x)
            d += g_partials[j];
        #pragma unroll
        for (int off = 16; off > 0; off >>= 1)
            d += __shfl_xor_sync(0xFFFFFFFFu, d, off);

        __shared__ double dwarp[16];
        if (lane == 0) dwarp[wid] = d;
        __syncthreads();
        if (wid == 0) {
            double t = (lane < 16) ? dwarp[lane] : 0.0;
            #pragma unroll
            for (int off = 16; off > 0; off >>= 1)
                t += __shfl_xor_sync(0xFFFFFFFFu, t, off);
            if (lane == 0) {
                out[0] = (float)(t * inv_rows);
                __threadfence();
                g_retire_count = 0;  // reset for next graph replay
            }
        }
    }
}

extern "C" void kernel_launch(void* const* d_in, const int* in_sizes, int n_in,
                              void* d_out, int out_size) {
    const float* probs     = (const float*)d_in[0];
    const float* centroids = (const float*)d_in[1];
    float* out = (float*)d_out;

    long long n = (long long)in_sizes[0];   // N*K total elements (~1.01e8)
    const int K = 101;
    long long rows = n / K;

    int n8 = (int)(n >> 3);                 // 8-float packet count (12,625,000)
    long long tail_start = (long long)n8 << 3;
    int n_tail = (int)(n - tail_start);     // 0 for this shape

    bins_combiner_kernel<<<NBLOCKS, 512>>>(
        probs, centroids, n8,
        probs + tail_start, centroids + tail_start, n_tail,
        out, 1.0 / (double)rows);
}

// round 8
// speedup vs baseline: 1.0592x; 1.0191x over previous
#include <cuda_runtime.h>

// Scratch via __device__ globals (no allocations allowed).
#define NBLOCKS 592    // 148 SMs x 4 resident CTAs -> exactly one wave
__device__ double g_partials[NBLOCKS];
__device__ unsigned int g_retire_count = 0;  // reset to 0 by last block each run

// 256-bit streaming load (sm_100+): one LDG.E.256 per 8 floats.
__device__ __forceinline__ void ldg256(const float* p, float* v) {
    asm volatile(
        "ld.global.nc.v8.f32 {%0, %1, %2, %3, %4, %5, %6, %7}, [%8];"
        : "=f"(v[0]), "=f"(v[1]), "=f"(v[2]), "=f"(v[3]),
          "=f"(v[4]), "=f"(v[5]), "=f"(v[6]), "=f"(v[7])
        : "l"(p));
}

// Single fused kernel, single wave: grid-stride over 32-byte packets with
// two independent 256-bit loads per iteration. Per-block partial into a
// dedicated slot; last retiring block reduces partials and writes the mean.
// Graph-replayable (retire counter self-resets).
__global__ void __launch_bounds__(512, 4)
bins_combiner_kernel(const float* __restrict__ p,
                     const float* __restrict__ c,
                     int n8,                      // count of 8-float packets
                     const float* __restrict__ p_tail,
                     const float* __restrict__ c_tail,
                     int n_tail,
                     float* __restrict__ out,
                     double inv_rows) {
    float acc0 = 0.0f, acc1 = 0.0f;

    int idx    = blockIdx.x * blockDim.x + threadIdx.x;
    int stride = gridDim.x * blockDim.x;   // 592*512 = 303104

    for (int i = idx; i < n8; i += stride) {
        float a[8], b[8];
        ldg256(p + (long long)i * 8, a);
        ldg256(c + (long long)i * 8, b);
        acc0 = fmaf(a[0], b[0], acc0);
        acc1 = fmaf(a[1], b[1], acc1);
        acc0 = fmaf(a[2], b[2], acc0);
        acc1 = fmaf(a[3], b[3], acc1);
        acc0 = fmaf(a[4], b[4], acc0);
        acc1 = fmaf(a[5], b[5], acc1);
        acc0 = fmaf(a[6], b[6], acc0);
        acc1 = fmaf(a[7], b[7], acc1);
    }

    float acc = acc0 + acc1;

    // Scalar tail (n divisible by 8 here -> n_tail==0; kept for generality).
    if (idx < n_tail) {
        acc = fmaf(p_tail[idx], c_tail[idx], acc);
    }

    // Warp reduction.
    #pragma unroll
    for (int off = 16; off > 0; off >>= 1)
        acc += __shfl_xor_sync(0xFFFFFFFFu, acc, off);

    // Block reduction via shared memory.
    __shared__ float warp_sums[16];  // 512 threads -> 16 warps
    __shared__ bool  is_last;
    int lane = threadIdx.x & 31;
    int wid  = threadIdx.x >> 5;
    if (lane == 0) warp_sums[wid] = acc;
    __syncthreads();

    if (wid == 0) {
        float v = (lane < 16) ? warp_sums[lane] : 0.0f;
        #pragma unroll
        for (int off = 16; off > 0; off >>= 1)
            v += __shfl_xor_sync(0xFFFFFFFFu, v, off);
        if (lane == 0) {
            g_partials[blockIdx.x] = (double)v;
            __threadfence();
            unsigned int prev = atomicAdd(&g_retire_count, 1u);
            is_last = (prev == gridDim.x - 1);
        }
    }
    __syncthreads();

    if (is_last) {
        __threadfence();  // acquire: make all partials visible
        // 592 doubles reduced across 512 threads (threads 0..79 take 2).
        double d = 0.0;
        for (unsigned int j = threadIdx.x; j < gridDim.x; j += blockDim.x)
            d += g_partials[j];
        #pragma unroll
        for (int off = 16; off > 0; off >>= 1)
            d += __shfl_xor_sync(0xFFFFFFFFu, d, off);

        __shared__ double dwarp[16];
        if (lane == 0) dwarp[wid] = d;
        __syncthreads();
        if (wid == 0) {
            double t = (lane < 16) ? dwarp[lane] : 0.0;
            #pragma unroll
            for (int off = 16; off > 0; off >>= 1)
                t += __shfl_xor_sync(0xFFFFFFFFu, t, off);
            if (lane == 0) {
                out[0] = (float)(t * inv_rows);
                __threadfence();
                g_retire_count = 0;  // reset for next graph replay
            }
        }
    }
}

extern "C" void kernel_launch(void* const* d_in, const int* in_sizes, int n_in,
                              void* d_out, int out_size) {
    const float* probs     = (const float*)d_in[0];
    const float* centroids = (const float*)d_in[1];
    float* out = (float*)d_out;

    long long n = (long long)in_sizes[0];   // N*K total elements (~1.01e8)
    const int K = 101;
    long long rows = n / K;

    int n8 = (int)(n >> 3);                 // 8-float packet count (12,625,000)
    long long tail_start = (long long)n8 << 3;
    int n_tail = (int)(n - tail_start);     // 0 for this shape

    bins_combiner_kernel<<<NBLOCKS, 512>>>(
        probs, centroids, n8,
        probs + tail_start, centroids + tail_start, n_tail,
        out, 1.0 / (double)rows);
}